// round 10
// baseline (speedup 1.0000x reference)
#include <cuda_runtime.h>
#include <cuda_bf16.h>
#include <cstdint>

#define B_   256
#define P_   4
#define D_   768
#define U_   32
#define IN_  3072

#define BM 128
#define BN 64
#define BK 32
#define NTILES (IN_ / BK)   // 96
#define THREADS 256

// smem strides (bytes): A rows 272, B rows 144 (proven conflict-free)
#define ROW_A   272
#define ROW_Bb  144
#define A_PLANE (32 * ROW_A)          // 8704
#define B_PLANE (32 * ROW_Bb)         // 4608
#define ST_AH   0
#define ST_AL   A_PLANE
#define ST_BH   (2 * A_PLANE)
#define ST_BL   (2 * A_PLANE + B_PLANE)
#define STAGE_SZ (2 * A_PLANE + 2 * B_PLANE)   // 26624
#define N_STAGES 3
#define SMEM_TOTAL (N_STAGES * STAGE_SZ)       // 79872 -> 2 CTAs/SM

// Pre-converted A, K-major: [IN_][B_] bf16 hi/lo planes (L2-resident, reused 384x)
__device__ __align__(16) __nv_bfloat16 g_Ahi[IN_ * B_];
__device__ __align__(16) __nv_bfloat16 g_Alo[IN_ * B_];

__device__ __forceinline__ uint32_t smem_u32(const void* p) {
    uint32_t a;
    asm("{ .reg .u64 t; cvta.to.shared.u64 t, %1; cvt.u32.u64 %0, t; }" : "=r"(a) : "l"(p));
    return a;
}
#define LDSM_X4T(r, addr) \
    asm volatile("ldmatrix.sync.aligned.m8n8.x4.trans.shared.b16 {%0,%1,%2,%3}, [%4];" \
        : "=r"((r)[0]), "=r"((r)[1]), "=r"((r)[2]), "=r"((r)[3]) : "r"(addr))
#define MMA16816(d, a, b0, b1) \
    asm volatile("mma.sync.aligned.m16n8k16.row.col.f32.bf16.bf16.f32 " \
        "{%0,%1,%2,%3}, {%4,%5,%6,%7}, {%8,%9}, {%0,%1,%2,%3};" \
        : "+f"((d)[0]), "+f"((d)[1]), "+f"((d)[2]), "+f"((d)[3]) \
        : "r"((a)[0]), "r"((a)[1]), "r"((a)[2]), "r"((a)[3]), "r"(b0), "r"(b1))

// hi = [bf16(y):bf16(x)], lo = residual pair
__device__ __forceinline__ void cvt_hilo2(float x, float y, uint32_t& hi, uint32_t& lo) {
    asm("cvt.rn.bf16x2.f32 %0, %1, %2;" : "=r"(hi) : "f"(y), "f"(x));
    float xh = __uint_as_float(hi << 16);
    float yh = __uint_as_float(hi & 0xffff0000u);
    float dx = x - xh;
    float dy = y - yh;
    asm("cvt.rn.bf16x2.f32 %0, %1, %2;" : "=r"(lo) : "f"(dy), "f"(dx));
}

// ---------------- Fused pre-pass: A -> K-major bf16 hi/lo planes + mean ----------------
__global__ void coldprompt_prep_mean(const float* __restrict__ A, float* __restrict__ mean_out)
{
    __shared__ float T[32][33];
    const int tid = threadIdx.x;
    const int b0  = blockIdx.x * 32;
    const int d0  = blockIdx.y * 32;

    const int bb  = tid >> 3;
    const int dd4 = (tid & 7) * 4;
    const int kk  = tid >> 3;
    const int bb4 = (tid & 7) * 4;

    float4 s = make_float4(0.f, 0.f, 0.f, 0.f);

    #pragma unroll
    for (int p = 0; p < P_; ++p) {
        float4 v = *(const float4*)(A + ((size_t)(b0 + bb) * P_ + p) * D_ + d0 + dd4);
        s.x += v.x; s.y += v.y; s.z += v.z; s.w += v.w;
        T[dd4 + 0][bb] = v.x;
        T[dd4 + 1][bb] = v.y;
        T[dd4 + 2][bb] = v.z;
        T[dd4 + 3][bb] = v.w;
        __syncthreads();
        {
            float x0 = T[kk][bb4 + 0], x1 = T[kk][bb4 + 1];
            float x2 = T[kk][bb4 + 2], x3 = T[kk][bb4 + 3];
            uint32_t h0, l0, h1, l1;
            cvt_hilo2(x0, x1, h0, l0);
            cvt_hilo2(x2, x3, h1, l1);
            const size_t o = (size_t)(p * D_ + d0 + kk) * B_ + b0 + bb4;
            *(uint2*)(g_Ahi + o) = make_uint2(h0, h1);
            *(uint2*)(g_Alo + o) = make_uint2(l0, l1);
        }
        __syncthreads();
    }
    s.x *= 0.25f; s.y *= 0.25f; s.z *= 0.25f; s.w *= 0.25f;
    *(float4*)(mean_out + (size_t)(b0 + bb) * D_ + d0 + dd4) = s;
}

// ---------------- Main GEMM: 3-stage, one sync/tile, 2 CTAs/SM ----------------
__global__ void __launch_bounds__(THREADS, 2)
coldprompt_mma_gemm(const float* __restrict__ W,     // [32, 3072, 768]
                    const float* __restrict__ bias,  // [32, 768]
                    float* __restrict__ C)           // [32*256, 768]
{
    extern __shared__ char smem[];
    const uint32_t sb = smem_u32(smem);

    const int tid  = threadIdx.x;
    const int wid  = tid >> 5;
    const int lane = tid & 31;
    const int u    = blockIdx.z;
    const int m0   = blockIdx.y * BM;
    const int n0   = blockIdx.x * BN;

    const int wm = (wid & 3) * 32;    // 4 m-warps of 32
    const int wn = (wid >> 2) * 32;   // 2 n-warps of 32

    const float* __restrict__ Wbase = W + (size_t)u * IN_ * D_ + n0;

    // A copy mapping: per plane 2 chunks of 16B
    const int a_row0 = tid >> 4;            // k-row 0..15 (chunk0), +16 (chunk1)
    const int a_c8   = (tid & 15) * 8;      // m elem offset (16B)
    // B load mapping: 2 float4 per thread
    const int b_kr0 = tid >> 4;             // 0..15 (+16 for c=1)
    const int b_n4  = (tid & 15) * 4;

    float acc[2][4][4];
    #pragma unroll
    for (int i = 0; i < 2; i++)
        #pragma unroll
        for (int j = 0; j < 4; j++) {
            acc[i][j][0] = 0.f; acc[i][j][1] = 0.f;
            acc[i][j][2] = 0.f; acc[i][j][3] = 0.f;
        }

    uint4  areg_h[2], areg_l[2];
    float4 breg[2];

    auto LOAD = [&](int it) {
        const int k0 = it * BK;
        #pragma unroll
        for (int c = 0; c < 2; ++c) {
            const int kr = a_row0 + c * 16;
            const size_t o = (size_t)(k0 + kr) * B_ + m0 + a_c8;
            areg_h[c] = *(const uint4*)(g_Ahi + o);
            areg_l[c] = *(const uint4*)(g_Alo + o);
        }
        #pragma unroll
        for (int c = 0; c < 2; ++c) {
            const int kr = b_kr0 + c * 16;
            breg[c] = *(const float4*)(Wbase + (size_t)(k0 + kr) * D_ + b_n4);
        }
    };

    auto STORE = [&](int s) {
        char* st = smem + s * STAGE_SZ;
        #pragma unroll
        for (int c = 0; c < 2; ++c) {
            const int kr = a_row0 + c * 16;
            char* p = st + kr * ROW_A + a_c8 * 2;
            *(uint4*)(p + ST_AH) = areg_h[c];
            *(uint4*)(p + ST_AL) = areg_l[c];
        }
        #pragma unroll
        for (int c = 0; c < 2; ++c) {
            const int kr = b_kr0 + c * 16;
            uint32_t h0, l0, h1, l1;
            cvt_hilo2(breg[c].x, breg[c].y, h0, l0);
            cvt_hilo2(breg[c].z, breg[c].w, h1, l1);
            char* p = st + kr * ROW_Bb + b_n4 * 2;
            *(uint2*)(p + ST_BH) = make_uint2(h0, h1);
            *(uint2*)(p + ST_BL) = make_uint2(l0, l1);
        }
    };

    // ldmatrix lane address components (proven mapping)
    const uint32_t a_krow = (lane & 7) + ((lane >> 4) & 1) * 8;
    const uint32_t a_mcol = ((lane >> 3) & 1) * 8;
    const uint32_t b_krow = (lane & 7) + ((lane >> 3) & 1) * 8;
    const uint32_t b_ncol = (lane >> 4) * 8;

    auto COMPUTE = [&](int s) {
        const uint32_t st = sb + s * STAGE_SZ;
        #pragma unroll
        for (int ks = 0; ks < 2; ++ks) {
            uint32_t a_hi[2][4], a_lo[2][4];
            #pragma unroll
            for (int mt = 0; mt < 2; ++mt) {
                const uint32_t ao =
                    (ks * 16 + a_krow) * ROW_A + (wm + mt * 16 + a_mcol) * 2;
                LDSM_X4T(a_hi[mt], st + ST_AH + ao);
                LDSM_X4T(a_lo[mt], st + ST_AL + ao);
            }
            uint32_t b_hi[8], b_lo[8];
            #pragma unroll
            for (int nt2 = 0; nt2 < 2; ++nt2) {
                const uint32_t bo =
                    (ks * 16 + b_krow) * ROW_Bb + (wn + nt2 * 16 + b_ncol) * 2;
                LDSM_X4T(&b_hi[nt2 * 4], st + ST_BH + bo);
                LDSM_X4T(&b_lo[nt2 * 4], st + ST_BL + bo);
            }
            #pragma unroll
            for (int mt = 0; mt < 2; ++mt)
                #pragma unroll
                for (int nt = 0; nt < 4; ++nt) {
                    MMA16816(acc[mt][nt], a_hi[mt], b_hi[nt * 2], b_hi[nt * 2 + 1]);
                    MMA16816(acc[mt][nt], a_hi[mt], b_lo[nt * 2], b_lo[nt * 2 + 1]);
                    MMA16816(acc[mt][nt], a_lo[mt], b_hi[nt * 2], b_hi[nt * 2 + 1]);
                }
        }
    };

    // ---- prologue: fill stages 0 and 1 ----
    LOAD(0); STORE(0);
    LOAD(1); STORE(1);
    __syncthreads();

    // ---- mainloop: ONE sync per tile, STORE never blocks COMPUTE ----
    int s = 0;                       // it % 3
    int s2 = 2;                      // (it+2) % 3
    #pragma unroll 1
    for (int it = 0; it < NTILES; ++it) {
        if (it + 2 < NTILES) LOAD(it + 2);
        COMPUTE(s);
        __syncthreads();             // all warps done reading stage s2's previous contents
        if (it + 2 < NTILES) STORE(s2);
        s  = (s  == 2) ? 0 : s + 1;
        s2 = (s2 == 2) ? 0 : s2 + 1;
    }

    // ---- epilogue ----
    const int g  = lane >> 2;
    const int tq = lane & 3;
    #pragma unroll
    for (int mt = 0; mt < 2; ++mt) {
        #pragma unroll
        for (int nt = 0; nt < 4; ++nt) {
            const int row0 = m0 + wm + mt * 16 + g;
            const int col  = n0 + wn + nt * 8 + tq * 2;
            const float2 bv = *(const float2*)(bias + (size_t)u * D_ + col);
            float* c0 = C + ((size_t)u * B_ + row0) * D_ + col;
            float* c1 = c0 + (size_t)8 * D_;
            float2 o0, o1;
            o0.x = acc[mt][nt][0] + bv.x;
            o0.y = acc[mt][nt][1] + bv.y;
            o1.x = acc[mt][nt][2] + bv.x;
            o1.y = acc[mt][nt][3] + bv.y;
            *(float2*)c0 = o0;
            *(float2*)c1 = o1;
        }
    }
}

extern "C" void kernel_launch(void* const* d_in, const int* in_sizes, int n_in,
                              void* d_out, int out_size)
{
    const float* weight = (const float*)d_in[0];
    const float* W_spec = (const float*)d_in[1];
    const float* b_spec = (const float*)d_in[2];
    float* out = (float*)d_out;

    cudaFuncSetAttribute(coldprompt_mma_gemm,
                         cudaFuncAttributeMaxDynamicSharedMemorySize, SMEM_TOTAL);

    dim3 pgrid(B_ / 32, D_ / 32);   // (8, 24)
    coldprompt_prep_mean<<<pgrid, 256>>>(weight, out + (size_t)U_ * B_ * D_);

    dim3 grid(D_ / BN, B_ / BM, U_);   // (12, 2, 32) = 768 CTAs, 2/SM
    coldprompt_mma_gemm<<<grid, THREADS, SMEM_TOTAL>>>(W_spec, b_spec, out);
}

// round 12
// speedup vs baseline: 1.0284x; 1.0284x over previous
#include <cuda_runtime.h>
#include <cuda_bf16.h>
#include <cstdint>

#define B_   256
#define P_   4
#define D_   768
#define U_   32
#define IN_  3072

#define BM 128
#define BN 96
#define BK 32
#define NTILES (IN_ / BK)   // 96
#define THREADS 256

// smem strides (bytes): A rows 272 (proven), B rows 208 (96 bf16 + 16 pad; odd multiple of 16 -> conflict-free)
#define ROW_A   272
#define ROW_Bb  208
#define A_PLANE (32 * ROW_A)          // 8704
#define B_PLANE (32 * ROW_Bb)         // 6656
#define ST_AH   0
#define ST_AL   A_PLANE
#define ST_BH   (2 * A_PLANE)
#define ST_BL   (2 * A_PLANE + B_PLANE)
#define STAGE_SZ (2 * A_PLANE + 2 * B_PLANE)   // 30720
#define SMEM_TOTAL (2 * STAGE_SZ)              // 61440 -> 2 CTAs/SM

// Pre-converted A, K-major: [IN_][B_] bf16 hi/lo planes (L2-resident, reused 256x)
__device__ __align__(16) __nv_bfloat16 g_Ahi[IN_ * B_];
__device__ __align__(16) __nv_bfloat16 g_Alo[IN_ * B_];

__device__ __forceinline__ uint32_t smem_u32(const void* p) {
    uint32_t a;
    asm("{ .reg .u64 t; cvta.to.shared.u64 t, %1; cvt.u32.u64 %0, t; }" : "=r"(a) : "l"(p));
    return a;
}
#define LDSM_X4T(r, addr) \
    asm volatile("ldmatrix.sync.aligned.m8n8.x4.trans.shared.b16 {%0,%1,%2,%3}, [%4];" \
        : "=r"((r)[0]), "=r"((r)[1]), "=r"((r)[2]), "=r"((r)[3]) : "r"(addr))
#define MMA16816(d, a, b0, b1) \
    asm volatile("mma.sync.aligned.m16n8k16.row.col.f32.bf16.bf16.f32 " \
        "{%0,%1,%2,%3}, {%4,%5,%6,%7}, {%8,%9}, {%0,%1,%2,%3};" \
        : "+f"((d)[0]), "+f"((d)[1]), "+f"((d)[2]), "+f"((d)[3]) \
        : "r"((a)[0]), "r"((a)[1]), "r"((a)[2]), "r"((a)[3]), "r"(b0), "r"(b1))

// hi = [bf16(y):bf16(x)], lo = residual pair
__device__ __forceinline__ void cvt_hilo2(float x, float y, uint32_t& hi, uint32_t& lo) {
    asm("cvt.rn.bf16x2.f32 %0, %1, %2;" : "=r"(hi) : "f"(y), "f"(x));
    float xh = __uint_as_float(hi << 16);
    float yh = __uint_as_float(hi & 0xffff0000u);
    float dx = x - xh;
    float dy = y - yh;
    asm("cvt.rn.bf16x2.f32 %0, %1, %2;" : "=r"(lo) : "f"(dy), "f"(dx));
}

// ---------------- Fused pre-pass: A -> K-major bf16 hi/lo planes + mean ----------------
__global__ void coldprompt_prep_mean(const float* __restrict__ A, float* __restrict__ mean_out)
{
    __shared__ float T[32][33];
    const int tid = threadIdx.x;
    const int b0  = blockIdx.x * 32;
    const int d0  = blockIdx.y * 32;

    const int bb  = tid >> 3;
    const int dd4 = (tid & 7) * 4;
    const int kk  = tid >> 3;
    const int bb4 = (tid & 7) * 4;

    float4 s = make_float4(0.f, 0.f, 0.f, 0.f);

    #pragma unroll
    for (int p = 0; p < P_; ++p) {
        float4 v = *(const float4*)(A + ((size_t)(b0 + bb) * P_ + p) * D_ + d0 + dd4);
        s.x += v.x; s.y += v.y; s.z += v.z; s.w += v.w;
        T[dd4 + 0][bb] = v.x;
        T[dd4 + 1][bb] = v.y;
        T[dd4 + 2][bb] = v.z;
        T[dd4 + 3][bb] = v.w;
        __syncthreads();
        {
            float x0 = T[kk][bb4 + 0], x1 = T[kk][bb4 + 1];
            float x2 = T[kk][bb4 + 2], x3 = T[kk][bb4 + 3];
            uint32_t h0, l0, h1, l1;
            cvt_hilo2(x0, x1, h0, l0);
            cvt_hilo2(x2, x3, h1, l1);
            const size_t o = (size_t)(p * D_ + d0 + kk) * B_ + b0 + bb4;
            *(uint2*)(g_Ahi + o) = make_uint2(h0, h1);
            *(uint2*)(g_Alo + o) = make_uint2(l0, l1);
        }
        __syncthreads();
    }
    s.x *= 0.25f; s.y *= 0.25f; s.z *= 0.25f; s.w *= 0.25f;
    *(float4*)(mean_out + (size_t)(b0 + bb) * D_ + d0 + dd4) = s;
}

// ---------------- Main GEMM: BN=96, warp 32x48, 2 CTAs/SM ----------------
__global__ void __launch_bounds__(THREADS, 2)
coldprompt_mma_gemm(const float* __restrict__ W,     // [32, 3072, 768]
                    const float* __restrict__ bias,  // [32, 768]
                    float* __restrict__ C)           // [32*256, 768]
{
    extern __shared__ char smem[];
    const uint32_t sb = smem_u32(smem);

    const int tid  = threadIdx.x;
    const int wid  = tid >> 5;
    const int lane = tid & 31;
    const int u    = blockIdx.z;
    const int m0   = blockIdx.y * BM;
    const int n0   = blockIdx.x * BN;

    const int wm = (wid & 3) * 32;    // 4 m-warps of 32
    const int wn = (wid >> 2) * 48;   // 2 n-warps of 48

    const float* __restrict__ Wbase = W + (size_t)u * IN_ * D_ + n0;

    // A copy mapping: per plane 2 chunks of 16B
    const int a_row0 = tid >> 4;            // k-row 0..15 (chunk0), +16 (chunk1)
    const int a_c8   = (tid & 15) * 8;      // m elem offset (16B)
    // B load mapping: 3 float4 per thread; kr = tid>>3, slot nq = (tid&7)+8c (each slot = 4 floats)
    const int b_kr = tid >> 3;              // 0..31
    const int b_nq = tid & 7;               // + 8c, c in 0..2

    float acc[2][6][4];
    #pragma unroll
    for (int i = 0; i < 2; i++)
        #pragma unroll
        for (int j = 0; j < 6; j++) {
            acc[i][j][0] = 0.f; acc[i][j][1] = 0.f;
            acc[i][j][2] = 0.f; acc[i][j][3] = 0.f;
        }

    uint4  areg_h[2], areg_l[2];
    float4 breg[3];

    auto LOAD = [&](int it) {
        const int k0 = it * BK;
        #pragma unroll
        for (int c = 0; c < 2; ++c) {
            const int kr = a_row0 + c * 16;
            const size_t o = (size_t)(k0 + kr) * B_ + m0 + a_c8;
            areg_h[c] = *(const uint4*)(g_Ahi + o);
            areg_l[c] = *(const uint4*)(g_Alo + o);
        }
        #pragma unroll
        for (int c = 0; c < 3; ++c)
            breg[c] = *(const float4*)(Wbase + (size_t)(k0 + b_kr) * D_ + (b_nq + 8 * c) * 4);
    };

    auto STORE = [&](int s) {
        char* st = smem + s * STAGE_SZ;
        #pragma unroll
        for (int c = 0; c < 2; ++c) {
            const int kr = a_row0 + c * 16;
            char* p = st + kr * ROW_A + a_c8 * 2;
            *(uint4*)(p + ST_AH) = areg_h[c];
            *(uint4*)(p + ST_AL) = areg_l[c];
        }
        #pragma unroll
        for (int c = 0; c < 3; ++c) {
            uint32_t h0, l0, h1, l1;
            cvt_hilo2(breg[c].x, breg[c].y, h0, l0);
            cvt_hilo2(breg[c].z, breg[c].w, h1, l1);
            // slot = 4 bf16 = 8 bytes (bf16 n-offset = (b_nq+8c)*4 elems * 2B)
            char* p = st + b_kr * ROW_Bb + (b_nq + 8 * c) * 8;
            *(uint2*)(p + ST_BH) = make_uint2(h0, h1);
            *(uint2*)(p + ST_BL) = make_uint2(l0, l1);
        }
    };

    // ldmatrix lane address components (proven mapping)
    const uint32_t a_krow = (lane & 7) + ((lane >> 4) & 1) * 8;
    const uint32_t a_mcol = ((lane >> 3) & 1) * 8;
    const uint32_t b_krow = (lane & 7) + ((lane >> 3) & 1) * 8;
    const uint32_t b_ncol = (lane >> 4) * 8;

    auto COMPUTE = [&](int s) {
        const uint32_t st = sb + s * STAGE_SZ;
        #pragma unroll
        for (int ks = 0; ks < 2; ++ks) {
            uint32_t a_hi[2][4], a_lo[2][4];
            #pragma unroll
            for (int mt = 0; mt < 2; ++mt) {
                const uint32_t ao =
                    (ks * 16 + a_krow) * ROW_A + (wm + mt * 16 + a_mcol) * 2;
                LDSM_X4T(a_hi[mt], st + ST_AH + ao);
                LDSM_X4T(a_lo[mt], st + ST_AL + ao);
            }
            uint32_t b_hi[12], b_lo[12];
            #pragma unroll
            for (int nt2 = 0; nt2 < 3; ++nt2) {
                const uint32_t bo =
                    (ks * 16 + b_krow) * ROW_Bb + (wn + nt2 * 16 + b_ncol) * 2;
                LDSM_X4T(&b_hi[nt2 * 4], st + ST_BH + bo);
                LDSM_X4T(&b_lo[nt2 * 4], st + ST_BL + bo);
            }
            #pragma unroll
            for (int mt = 0; mt < 2; ++mt)
                #pragma unroll
                for (int nt = 0; nt < 6; ++nt) {
                    MMA16816(acc[mt][nt], a_hi[mt], b_hi[nt * 2], b_hi[nt * 2 + 1]);
                    MMA16816(acc[mt][nt], a_hi[mt], b_lo[nt * 2], b_lo[nt * 2 + 1]);
                    MMA16816(acc[mt][nt], a_lo[mt], b_hi[nt * 2], b_hi[nt * 2 + 1]);
                }
        }
    };

    // ---- pipeline (R9 skeleton, proven) ----
    LOAD(0);
    STORE(0);
    __syncthreads();

    #pragma unroll 1
    for (int it = 0; it < NTILES; ++it) {
        if (it + 1 < NTILES) LOAD(it + 1);
        COMPUTE(it & 1);
        if (it + 1 < NTILES) {
            __syncthreads();
            STORE((it + 1) & 1);
            __syncthreads();
        }
    }

    // ---- epilogue ----
    const int g  = lane >> 2;
    const int tq = lane & 3;
    #pragma unroll
    for (int mt = 0; mt < 2; ++mt) {
        #pragma unroll
        for (int nt = 0; nt < 6; ++nt) {
            const int row0 = m0 + wm + mt * 16 + g;
            const int col  = n0 + wn + nt * 8 + tq * 2;
            const float2 bv = *(const float2*)(bias + (size_t)u * D_ + col);
            float* c0 = C + ((size_t)u * B_ + row0) * D_ + col;
            float* c1 = c0 + (size_t)8 * D_;
            float2 o0, o1;
            o0.x = acc[mt][nt][0] + bv.x;
            o0.y = acc[mt][nt][1] + bv.y;
            o1.x = acc[mt][nt][2] + bv.x;
            o1.y = acc[mt][nt][3] + bv.y;
            *(float2*)c0 = o0;
            *(float2*)c1 = o1;
        }
    }
}

extern "C" void kernel_launch(void* const* d_in, const int* in_sizes, int n_in,
                              void* d_out, int out_size)
{
    const float* weight = (const float*)d_in[0];
    const float* W_spec = (const float*)d_in[1];
    const float* b_spec = (const float*)d_in[2];
    float* out = (float*)d_out;

    cudaFuncSetAttribute(coldprompt_mma_gemm,
                         cudaFuncAttributeMaxDynamicSharedMemorySize, SMEM_TOTAL);

    dim3 pgrid(B_ / 32, D_ / 32);   // (8, 24)
    coldprompt_prep_mean<<<pgrid, 256>>>(weight, out + (size_t)U_ * B_ * D_);

    dim3 grid(D_ / BN, B_ / BM, U_);   // (8, 2, 32) = 512 CTAs, 2/SM
    coldprompt_mma_gemm<<<grid, THREADS, SMEM_TOTAL>>>(W_spec, b_spec, out);
}

// round 13
// speedup vs baseline: 1.4116x; 1.3727x over previous
#include <cuda_runtime.h>
#include <cuda_fp16.h>
#include <cstdint>

#define B_   256
#define P_   4
#define D_   768
#define U_   32
#define IN_  3072

#define BM 128
#define BN 96
#define BK 32
#define NTILES (IN_ / BK)   // 96
#define THREADS 256

// smem strides (bytes): A rows 272 = 128 fp16 + 16 pad; B rows 208 = 96 fp16 + 16 pad (odd*16 -> conflict-free)
#define ROW_A   272
#define ROW_Bb  208
#define A_PLANE (32 * ROW_A)          // 8704
#define B_PLANE (32 * ROW_Bb)         // 6656
#define ST_A    0
#define ST_B    A_PLANE
#define STAGE_SZ (A_PLANE + B_PLANE)  // 15360
#define SMEM_TOTAL (2 * STAGE_SZ)     // 30720 -> 3 CTAs/SM

// Pre-converted A, K-major: [IN_][B_] fp16 (L2-resident, reused 256x)
__device__ __align__(16) __half g_Ah[IN_ * B_];

__device__ __forceinline__ uint32_t smem_u32(const void* p) {
    uint32_t a;
    asm("{ .reg .u64 t; cvta.to.shared.u64 t, %1; cvt.u32.u64 %0, t; }" : "=r"(a) : "l"(p));
    return a;
}
#define LDSM_X4T(r, addr) \
    asm volatile("ldmatrix.sync.aligned.m8n8.x4.trans.shared.b16 {%0,%1,%2,%3}, [%4];" \
        : "=r"((r)[0]), "=r"((r)[1]), "=r"((r)[2]), "=r"((r)[3]) : "r"(addr))
#define MMA16816F16(d, a, b0, b1) \
    asm volatile("mma.sync.aligned.m16n8k16.row.col.f32.f16.f16.f32 " \
        "{%0,%1,%2,%3}, {%4,%5,%6,%7}, {%8,%9}, {%0,%1,%2,%3};" \
        : "+f"((d)[0]), "+f"((d)[1]), "+f"((d)[2]), "+f"((d)[3]) \
        : "r"((a)[0]), "r"((a)[1]), "r"((a)[2]), "r"((a)[3]), "r"(b0), "r"(b1))

__device__ __forceinline__ uint32_t pack_h2(float x, float y) {
    __half2 h = __floats2half2_rn(x, y);
    return *reinterpret_cast<uint32_t*>(&h);
}

// ---------------- Fused pre-pass: A -> K-major fp16 + mean ----------------
__global__ void coldprompt_prep_mean(const float* __restrict__ A, float* __restrict__ mean_out)
{
    __shared__ float T[32][33];
    const int tid = threadIdx.x;
    const int b0  = blockIdx.x * 32;
    const int d0  = blockIdx.y * 32;

    const int bb  = tid >> 3;
    const int dd4 = (tid & 7) * 4;
    const int kk  = tid >> 3;
    const int bb4 = (tid & 7) * 4;

    float4 s = make_float4(0.f, 0.f, 0.f, 0.f);

    #pragma unroll
    for (int p = 0; p < P_; ++p) {
        float4 v = *(const float4*)(A + ((size_t)(b0 + bb) * P_ + p) * D_ + d0 + dd4);
        s.x += v.x; s.y += v.y; s.z += v.z; s.w += v.w;
        T[dd4 + 0][bb] = v.x;
        T[dd4 + 1][bb] = v.y;
        T[dd4 + 2][bb] = v.z;
        T[dd4 + 3][bb] = v.w;
        __syncthreads();
        {
            float x0 = T[kk][bb4 + 0], x1 = T[kk][bb4 + 1];
            float x2 = T[kk][bb4 + 2], x3 = T[kk][bb4 + 3];
            const size_t o = (size_t)(p * D_ + d0 + kk) * B_ + b0 + bb4;
            *(uint2*)(g_Ah + o) = make_uint2(pack_h2(x0, x1), pack_h2(x2, x3));
        }
        __syncthreads();
    }
    s.x *= 0.25f; s.y *= 0.25f; s.z *= 0.25f; s.w *= 0.25f;
    *(float4*)(mean_out + (size_t)(b0 + bb) * D_ + d0 + dd4) = s;
}

// ---------------- Main GEMM: fp16 single-pass, BN=96, warp 32x48 ----------------
__global__ void __launch_bounds__(THREADS, 3)
coldprompt_mma_gemm(const float* __restrict__ W,     // [32, 3072, 768]
                    const float* __restrict__ bias,  // [32, 768]
                    float* __restrict__ C)           // [32*256, 768]
{
    extern __shared__ char smem[];
    const uint32_t sb = smem_u32(smem);

    const int tid  = threadIdx.x;
    const int wid  = tid >> 5;
    const int lane = tid & 31;
    const int u    = blockIdx.z;
    const int m0   = blockIdx.y * BM;
    const int n0   = blockIdx.x * BN;

    const int wm = (wid & 3) * 32;    // 4 m-warps of 32
    const int wn = (wid >> 2) * 48;   // 2 n-warps of 48

    const float* __restrict__ Wbase = W + (size_t)u * IN_ * D_ + n0;

    // A copy mapping: 2 chunks of 16B (8 fp16)
    const int a_row0 = tid >> 4;            // k-row 0..15 (chunk0), +16 (chunk1)
    const int a_c8   = (tid & 15) * 8;      // m elem offset
    // B load mapping: 3 float4 per thread; kr = tid>>3, slot nq = (tid&7)+8c (slot = 4 floats)
    const int b_kr = tid >> 3;              // 0..31
    const int b_nq = tid & 7;               // + 8c, c in 0..2

    float acc[2][6][4];
    #pragma unroll
    for (int i = 0; i < 2; i++)
        #pragma unroll
        for (int j = 0; j < 6; j++) {
            acc[i][j][0] = 0.f; acc[i][j][1] = 0.f;
            acc[i][j][2] = 0.f; acc[i][j][3] = 0.f;
        }

    uint4  areg[2];
    float4 breg[3];

    auto LOAD = [&](int it) {
        const int k0 = it * BK;
        #pragma unroll
        for (int c = 0; c < 2; ++c) {
            const int kr = a_row0 + c * 16;
            areg[c] = *(const uint4*)(g_Ah + (size_t)(k0 + kr) * B_ + m0 + a_c8);
        }
        #pragma unroll
        for (int c = 0; c < 3; ++c)
            breg[c] = *(const float4*)(Wbase + (size_t)(k0 + b_kr) * D_ + (b_nq + 8 * c) * 4);
    };

    auto STORE = [&](int s) {
        char* st = smem + s * STAGE_SZ;
        #pragma unroll
        for (int c = 0; c < 2; ++c) {
            const int kr = a_row0 + c * 16;
            *(uint4*)(st + ST_A + kr * ROW_A + a_c8 * 2) = areg[c];
        }
        #pragma unroll
        for (int c = 0; c < 3; ++c) {
            char* p = st + ST_B + b_kr * ROW_Bb + (b_nq + 8 * c) * 8;
            *(uint2*)p = make_uint2(pack_h2(breg[c].x, breg[c].y),
                                    pack_h2(breg[c].z, breg[c].w));
        }
    };

    // ldmatrix lane address components (proven mapping)
    const uint32_t a_krow = (lane & 7) + ((lane >> 4) & 1) * 8;
    const uint32_t a_mcol = ((lane >> 3) & 1) * 8;
    const uint32_t b_krow = (lane & 7) + ((lane >> 3) & 1) * 8;
    const uint32_t b_ncol = (lane >> 4) * 8;

    auto COMPUTE = [&](int s) {
        const uint32_t st = sb + s * STAGE_SZ;
        #pragma unroll
        for (int ks = 0; ks < 2; ++ks) {
            uint32_t a[2][4];
            #pragma unroll
            for (int mt = 0; mt < 2; ++mt) {
                const uint32_t ao =
                    (ks * 16 + a_krow) * ROW_A + (wm + mt * 16 + a_mcol) * 2;
                LDSM_X4T(a[mt], st + ST_A + ao);
            }
            uint32_t b[12];
            #pragma unroll
            for (int nt2 = 0; nt2 < 3; ++nt2) {
                const uint32_t bo =
                    (ks * 16 + b_krow) * ROW_Bb + (wn + nt2 * 16 + b_ncol) * 2;
                LDSM_X4T(&b[nt2 * 4], st + ST_B + bo);
            }
            #pragma unroll
            for (int mt = 0; mt < 2; ++mt)
                #pragma unroll
                for (int nt = 0; nt < 6; ++nt)
                    MMA16816F16(acc[mt][nt], a[mt], b[nt * 2], b[nt * 2 + 1]);
        }
    };

    // ---- pipeline (R9/R12 skeleton, proven) ----
    LOAD(0);
    STORE(0);
    __syncthreads();

    #pragma unroll 1
    for (int it = 0; it < NTILES; ++it) {
        if (it + 1 < NTILES) LOAD(it + 1);
        COMPUTE(it & 1);
        if (it + 1 < NTILES) {
            __syncthreads();
            STORE((it + 1) & 1);
            __syncthreads();
        }
    }

    // ---- epilogue ----
    const int g  = lane >> 2;
    const int tq = lane & 3;
    #pragma unroll
    for (int mt = 0; mt < 2; ++mt) {
        #pragma unroll
        for (int nt = 0; nt < 6; ++nt) {
            const int row0 = m0 + wm + mt * 16 + g;
            const int col  = n0 + wn + nt * 8 + tq * 2;
            const float2 bv = *(const float2*)(bias + (size_t)u * D_ + col);
            float* c0 = C + ((size_t)u * B_ + row0) * D_ + col;
            float* c1 = c0 + (size_t)8 * D_;
            float2 o0, o1;
            o0.x = acc[mt][nt][0] + bv.x;
            o0.y = acc[mt][nt][1] + bv.y;
            o1.x = acc[mt][nt][2] + bv.x;
            o1.y = acc[mt][nt][3] + bv.y;
            *(float2*)c0 = o0;
            *(float2*)c1 = o1;
        }
    }
}

extern "C" void kernel_launch(void* const* d_in, const int* in_sizes, int n_in,
                              void* d_out, int out_size)
{
    const float* weight = (const float*)d_in[0];
    const float* W_spec = (const float*)d_in[1];
    const float* b_spec = (const float*)d_in[2];
    float* out = (float*)d_out;

    cudaFuncSetAttribute(coldprompt_mma_gemm,
                         cudaFuncAttributeMaxDynamicSharedMemorySize, SMEM_TOTAL);

    dim3 pgrid(B_ / 32, D_ / 32);   // (8, 24)
    coldprompt_prep_mean<<<pgrid, 256>>>(weight, out + (size_t)U_ * B_ * D_);

    dim3 grid(D_ / BN, B_ / BM, U_);   // (8, 2, 32) = 512 CTAs
    coldprompt_mma_gemm<<<grid, THREADS, SMEM_TOTAL>>>(W_spec, b_spec, out);
}

// round 14
// speedup vs baseline: 1.9507x; 1.3819x over previous
#include <cuda_runtime.h>
#include <cuda_fp16.h>
#include <cstdint>

#define B_   256
#define P_   4
#define D_   768
#define U_   32
#define IN_  3072

#define BM 128
#define BN 96
#define BK 32
#define NTILES (IN_ / BK)   // 96
#define THREADS 128

// smem strides (bytes): A rows 272 = 128 fp16 + 16 pad; B rows 208 = 96 fp16 + 16 pad (odd*16 -> conflict-free)
#define ROW_A   272
#define ROW_Bb  208
#define A_PLANE (32 * ROW_A)          // 8704
#define B_PLANE (32 * ROW_Bb)         // 6656
#define ST_A    0
#define ST_B    A_PLANE
#define STAGE_SZ (A_PLANE + B_PLANE)  // 15360
#define SMEM_TOTAL (2 * STAGE_SZ)     // 30720

// Pre-converted A, K-major: [IN_][B_] fp16 (L2-resident, reused 256x)
__device__ __align__(16) __half g_Ah[IN_ * B_];

__device__ __forceinline__ uint32_t smem_u32(const void* p) {
    uint32_t a;
    asm("{ .reg .u64 t; cvta.to.shared.u64 t, %1; cvt.u32.u64 %0, t; }" : "=r"(a) : "l"(p));
    return a;
}
#define LDSM_X4T(r, addr) \
    asm volatile("ldmatrix.sync.aligned.m8n8.x4.trans.shared.b16 {%0,%1,%2,%3}, [%4];" \
        : "=r"((r)[0]), "=r"((r)[1]), "=r"((r)[2]), "=r"((r)[3]) : "r"(addr))
#define MMA16816F16(d, a, b0, b1) \
    asm volatile("mma.sync.aligned.m16n8k16.row.col.f32.f16.f16.f32 " \
        "{%0,%1,%2,%3}, {%4,%5,%6,%7}, {%8,%9}, {%0,%1,%2,%3};" \
        : "+f"((d)[0]), "+f"((d)[1]), "+f"((d)[2]), "+f"((d)[3]) \
        : "r"((a)[0]), "r"((a)[1]), "r"((a)[2]), "r"((a)[3]), "r"(b0), "r"(b1))

__device__ __forceinline__ uint32_t pack_h2(float x, float y) {
    __half2 h = __floats2half2_rn(x, y);
    return *reinterpret_cast<uint32_t*>(&h);
}

// ---------------- Fused pre-pass: A -> K-major fp16 + mean ----------------
__global__ void coldprompt_prep_mean(const float* __restrict__ A, float* __restrict__ mean_out)
{
    __shared__ float T[32][33];
    const int tid = threadIdx.x;
    const int b0  = blockIdx.x * 32;
    const int d0  = blockIdx.y * 32;

    const int bb  = tid >> 3;
    const int dd4 = (tid & 7) * 4;
    const int kk  = tid >> 3;
    const int bb4 = (tid & 7) * 4;

    float4 s = make_float4(0.f, 0.f, 0.f, 0.f);

    #pragma unroll
    for (int p = 0; p < P_; ++p) {
        float4 v = *(const float4*)(A + ((size_t)(b0 + bb) * P_ + p) * D_ + d0 + dd4);
        s.x += v.x; s.y += v.y; s.z += v.z; s.w += v.w;
        T[dd4 + 0][bb] = v.x;
        T[dd4 + 1][bb] = v.y;
        T[dd4 + 2][bb] = v.z;
        T[dd4 + 3][bb] = v.w;
        __syncthreads();
        {
            float x0 = T[kk][bb4 + 0], x1 = T[kk][bb4 + 1];
            float x2 = T[kk][bb4 + 2], x3 = T[kk][bb4 + 3];
            const size_t o = (size_t)(p * D_ + d0 + kk) * B_ + b0 + bb4;
            *(uint2*)(g_Ah + o) = make_uint2(pack_h2(x0, x1), pack_h2(x2, x3));
        }
        __syncthreads();
    }
    s.x *= 0.25f; s.y *= 0.25f; s.z *= 0.25f; s.w *= 0.25f;
    *(float4*)(mean_out + (size_t)(b0 + bb) * D_ + d0 + dd4) = s;
}

// ---------------- Main GEMM: fp16, 4 warps, warp tile 64x48 ----------------
__global__ void __launch_bounds__(THREADS, 2)
coldprompt_mma_gemm(const float* __restrict__ W,     // [32, 3072, 768]
                    const float* __restrict__ bias,  // [32, 768]
                    float* __restrict__ C)           // [32*256, 768]
{
    extern __shared__ char smem[];
    const uint32_t sb = smem_u32(smem);

    const int tid  = threadIdx.x;
    const int wid  = tid >> 5;
    const int lane = tid & 31;
    const int u    = blockIdx.z;
    const int m0   = blockIdx.y * BM;
    const int n0   = blockIdx.x * BN;

    const int wm = (wid >> 1) * 64;   // 2 m-warps of 64
    const int wn = (wid & 1) * 48;    // 2 n-warps of 48

    const float* __restrict__ Wbase = W + (size_t)u * IN_ * D_ + n0;

    // A copy mapping: 4 chunks of 16B (8 fp16); idx = tid + 128c
    //   kr = idx>>4 (k-row), m8 = (idx&15)*8
    // B load mapping: 6 float4 per thread; idx = tid + 128c; kr = idx/24, slot = idx%24
    float acc[4][6][4];
    #pragma unroll
    for (int i = 0; i < 4; i++)
        #pragma unroll
        for (int j = 0; j < 6; j++) {
            acc[i][j][0] = 0.f; acc[i][j][1] = 0.f;
            acc[i][j][2] = 0.f; acc[i][j][3] = 0.f;
        }

    uint4  areg[4];
    float4 breg[6];

    auto LOAD = [&](int it) {
        const int k0 = it * BK;
        #pragma unroll
        for (int c = 0; c < 4; ++c) {
            const int idx = tid + THREADS * c;
            const int kr  = idx >> 4;
            const int m8  = (idx & 15) * 8;
            areg[c] = *(const uint4*)(g_Ah + (size_t)(k0 + kr) * B_ + m0 + m8);
        }
        #pragma unroll
        for (int c = 0; c < 6; ++c) {
            const int idx  = tid + THREADS * c;
            const int kr   = idx / 24;
            const int slot = idx - kr * 24;
            breg[c] = *(const float4*)(Wbase + (size_t)(k0 + kr) * D_ + slot * 4);
        }
    };

    auto STORE = [&](int s) {
        char* st = smem + s * STAGE_SZ;
        #pragma unroll
        for (int c = 0; c < 4; ++c) {
            const int idx = tid + THREADS * c;
            const int kr  = idx >> 4;
            const int m8  = (idx & 15) * 8;
            *(uint4*)(st + ST_A + kr * ROW_A + m8 * 2) = areg[c];
        }
        #pragma unroll
        for (int c = 0; c < 6; ++c) {
            const int idx  = tid + THREADS * c;
            const int kr   = idx / 24;
            const int slot = idx - kr * 24;
            char* p = st + ST_B + kr * ROW_Bb + slot * 8;
            *(uint2*)p = make_uint2(pack_h2(breg[c].x, breg[c].y),
                                    pack_h2(breg[c].z, breg[c].w));
        }
    };

    // ldmatrix lane address components (proven mapping)
    const uint32_t a_krow = (lane & 7) + ((lane >> 4) & 1) * 8;
    const uint32_t a_mcol = ((lane >> 3) & 1) * 8;
    const uint32_t b_krow = (lane & 7) + ((lane >> 3) & 1) * 8;
    const uint32_t b_ncol = (lane >> 4) * 8;

    auto COMPUTE = [&](int s) {
        const uint32_t st = sb + s * STAGE_SZ;
        #pragma unroll
        for (int ks = 0; ks < 2; ++ks) {
            uint32_t a[4][4];
            #pragma unroll
            for (int mt = 0; mt < 4; ++mt) {
                const uint32_t ao =
                    (ks * 16 + a_krow) * ROW_A + (wm + mt * 16 + a_mcol) * 2;
                LDSM_X4T(a[mt], st + ST_A + ao);
            }
            uint32_t b[12];
            #pragma unroll
            for (int nt2 = 0; nt2 < 3; ++nt2) {
                const uint32_t bo =
                    (ks * 16 + b_krow) * ROW_Bb + (wn + nt2 * 16 + b_ncol) * 2;
                LDSM_X4T(&b[nt2 * 4], st + ST_B + bo);
            }
            #pragma unroll
            for (int mt = 0; mt < 4; ++mt)
                #pragma unroll
                for (int nt = 0; nt < 6; ++nt)
                    MMA16816F16(acc[mt][nt], a[mt], b[nt * 2], b[nt * 2 + 1]);
        }
    };

    // ---- pipeline (R9 skeleton, proven) ----
    LOAD(0);
    STORE(0);
    __syncthreads();

    #pragma unroll 1
    for (int it = 0; it < NTILES; ++it) {
        if (it + 1 < NTILES) LOAD(it + 1);
        COMPUTE(it & 1);
        if (it + 1 < NTILES) {
            __syncthreads();
            STORE((it + 1) & 1);
            __syncthreads();
        }
    }

    // ---- epilogue ----
    const int g  = lane >> 2;
    const int tq = lane & 3;
    #pragma unroll
    for (int mt = 0; mt < 4; ++mt) {
        #pragma unroll
        for (int nt = 0; nt < 6; ++nt) {
            const int row0 = m0 + wm + mt * 16 + g;
            const int col  = n0 + wn + nt * 8 + tq * 2;
            const float2 bv = *(const float2*)(bias + (size_t)u * D_ + col);
            float* c0 = C + ((size_t)u * B_ + row0) * D_ + col;
            float* c1 = c0 + (size_t)8 * D_;
            float2 o0, o1;
            o0.x = acc[mt][nt][0] + bv.x;
            o0.y = acc[mt][nt][1] + bv.y;
            o1.x = acc[mt][nt][2] + bv.x;
            o1.y = acc[mt][nt][3] + bv.y;
            *(float2*)c0 = o0;
            *(float2*)c1 = o1;
        }
    }
}

extern "C" void kernel_launch(void* const* d_in, const int* in_sizes, int n_in,
                              void* d_out, int out_size)
{
    const float* weight = (const float*)d_in[0];
    const float* W_spec = (const float*)d_in[1];
    const float* b_spec = (const float*)d_in[2];
    float* out = (float*)d_out;

    cudaFuncSetAttribute(coldprompt_mma_gemm,
                         cudaFuncAttributeMaxDynamicSharedMemorySize, SMEM_TOTAL);

    dim3 pgrid(B_ / 32, D_ / 32);   // (8, 24)
    coldprompt_prep_mean<<<pgrid, 256>>>(weight, out + (size_t)U_ * B_ * D_);

    dim3 grid(D_ / BN, B_ / BM, U_);   // (8, 2, 32) = 512 CTAs
    coldprompt_mma_gemm<<<grid, THREADS, SMEM_TOTAL>>>(W_spec, b_spec, out);
}